// round 2
// baseline (speedup 1.0000x reference)
#include <cuda_runtime.h>

#define N_NODES 50000
#define DS 127
#define DPAD 128
#define NE 800000
#define EPSF 1e-7f
#define GEMM_ROWS 64

// Padded scratch (stride 128 floats). Column 127 is padding:
//  - g_h  : kept 0
//  - g_z  : kept 0
//  - g_agg: accumulates garbage from padded atomics, never read
__device__ __align__(16) float g_h[N_NODES * DPAD];
__device__ __align__(16) float g_z[N_NODES * DPAD];
__device__ __align__(16) float g_agg[N_NODES * DPAD];

__device__ __forceinline__ float warp_sum(float v) {
#pragma unroll
    for (int o = 16; o; o >>= 1) v += __shfl_xor_sync(0xffffffffu, v, o);
    return v;
}

// h = logmap0(expmap0(v)) for one row; lane holds cols lane, lane+32, lane+64, lane+96.
// Caller guarantees v[j]==0 for cols >= DS.
__device__ __forceinline__ void chain4(float v[4]) {
    float n2 = v[0]*v[0] + v[1]*v[1] + v[2]*v[2] + v[3]*v[3];
    n2 = warp_sum(n2);
    float n  = fmaxf(sqrtf(n2), EPSF);
    float t  = coshf(n);
    float f1 = sinhf(n) / n;
    float s[4];
    float ss = 0.f;
#pragma unroll
    for (int j = 0; j < 4; j++) { s[j] = f1 * v[j]; ss += s[j] * s[j]; }
    ss = warp_sum(ss);
    float ns = fmaxf(sqrtf(ss), EPSF);
    float d  = acoshf(fmaxf(t, 1.0f + EPSF));
    float f2 = d / ns;
#pragma unroll
    for (int j = 0; j < 4; j++) v[j] = f2 * s[j];
}

// h0 = logmap0(expmap0(x)); x is UNPADDED (stride 127)
__global__ void k_init(const float* __restrict__ x) {
    int warp = (blockIdx.x * blockDim.x + threadIdx.x) >> 5;
    int lane = threadIdx.x & 31;
    if (warp >= N_NODES) return;
    float v[4];
#pragma unroll
    for (int j = 0; j < 4; j++) {
        int c = lane + 32 * j;
        v[j] = (c < DS) ? x[warp * DS + c] : 0.f;
    }
    chain4(v);
#pragma unroll
    for (int j = 0; j < 4; j++) {
        int c = lane + 32 * j;
        g_h[warp * DPAD + c] = (c < DS) ? v[j] : 0.f;
    }
}

// z = h @ W + b (cols 0..126), z[:,127]=0. Also zeroes agg for the same rows.
// Block: 256 threads, 64 rows. Thread (cx=tid&31, ry=tid>>5) computes 8 rows x 4 cols.
extern __shared__ float smem[];
__global__ void k_gemm(const float* __restrict__ W, const float* __restrict__ b) {
    float* W_s = smem;                      // 127*128 floats
    float* h_s = smem + DS * DPAD;          // 64*128 floats
    float* b_s = h_s + GEMM_ROWS * DPAD;    // 128 floats
    int tid = threadIdx.x;

    // Load W (pad col 127 -> 0)
    for (int i = tid; i < DS * DPAD; i += 256) {
        int k = i >> 7, j = i & 127;
        W_s[i] = (j < DS) ? W[k * DS + j] : 0.f;
    }
    if (tid < DPAD) b_s[tid] = (tid < DS) ? b[tid] : 0.f;

    int row0 = blockIdx.x * GEMM_ROWS;
    const float4* h4  = (const float4*)g_h;
    float4*       hs4 = (float4*)h_s;
    for (int i = tid; i < GEMM_ROWS * 32; i += 256) {
        int r = i >> 5, q = i & 31;
        int row = row0 + r;
        hs4[i] = (row < N_NODES) ? h4[row * 32 + q] : make_float4(0.f, 0.f, 0.f, 0.f);
    }
    __syncthreads();

    int cx = tid & 31;
    int ry = tid >> 5;
    float4 acc[8];
#pragma unroll
    for (int r = 0; r < 8; r++) acc[r] = make_float4(0.f, 0.f, 0.f, 0.f);

    const float4* W4 = (const float4*)W_s;
#pragma unroll 4
    for (int k = 0; k < DS; k++) {
        float4 w = W4[k * 32 + cx];
#pragma unroll
        for (int r = 0; r < 8; r++) {
            float hv = h_s[(ry * 8 + r) * DPAD + k];  // warp-uniform broadcast
            acc[r].x += hv * w.x;
            acc[r].y += hv * w.y;
            acc[r].z += hv * w.z;
            acc[r].w += hv * w.w;
        }
    }

    float4 bb = ((const float4*)b_s)[cx];
    float4* z4 = (float4*)g_z;
    float4* a4 = (float4*)g_agg;
#pragma unroll
    for (int r = 0; r < 8; r++) {
        int row = row0 + ry * 8 + r;
        if (row < N_NODES) {
            float4 o;
            o.x = acc[r].x + bb.x;
            o.y = acc[r].y + bb.y;
            o.z = acc[r].z + bb.z;
            o.w = acc[r].w + bb.w;
            z4[row * 32 + cx] = o;
            a4[row * 32 + cx] = make_float4(0.f, 0.f, 0.f, 0.f);
        }
    }
}

// Warp-per-edge: agg[dst] += w * z[src], 32 lanes x float4 vector reductions.
__global__ void k_edge(const int* __restrict__ src, const int* __restrict__ dst,
                       const float* __restrict__ wt) {
    int g = blockIdx.x * blockDim.x + threadIdx.x;
    int e = g >> 5, lane = g & 31;
    if (e >= NE) return;
    int s = src[e];
    int d = dst[e];
    float w = wt[e];
    const float4* z4 = (const float4*)g_z;
    float4 v = z4[s * 32 + lane];
    float4* a = (float4*)g_agg + d * 32 + lane;
    asm volatile("red.global.add.v4.f32 [%0], {%1,%2,%3,%4};"
                 :: "l"(a), "f"(v.x * w), "f"(v.y * w), "f"(v.z * w), "f"(v.w * w)
                 : "memory");
}

// h = logmap0(expmap0(relu(agg) + h))
__global__ void k_post() {
    int warp = (blockIdx.x * blockDim.x + threadIdx.x) >> 5;
    int lane = threadIdx.x & 31;
    if (warp >= N_NODES) return;
    float v[4];
#pragma unroll
    for (int j = 0; j < 4; j++) {
        int c = lane + 32 * j;
        float a = g_agg[warp * DPAD + c];
        float h = g_h[warp * DPAD + c];
        v[j] = (c < DS) ? (fmaxf(a, 0.f) + h) : 0.f;
    }
    chain4(v);
#pragma unroll
    for (int j = 0; j < 4; j++) {
        int c = lane + 32 * j;
        g_h[warp * DPAD + c] = (c < DS) ? v[j] : 0.f;
    }
}

// out = expmap0(h): out[i,0]=cosh(n), out[i,1+j]=sinh(n)*h_j/n  (row stride 128)
__global__ void k_final(float* __restrict__ out) {
    int warp = (blockIdx.x * blockDim.x + threadIdx.x) >> 5;
    int lane = threadIdx.x & 31;
    if (warp >= N_NODES) return;
    float v[4];
#pragma unroll
    for (int j = 0; j < 4; j++) {
        int c = lane + 32 * j;
        v[j] = g_h[warp * DPAD + c];  // pad col already 0
    }
    float n2 = v[0]*v[0] + v[1]*v[1] + v[2]*v[2] + v[3]*v[3];
    n2 = warp_sum(n2);
    float n = fmaxf(sqrtf(n2), EPSF);
    float t = coshf(n);
    float f = sinhf(n) / n;
    if (lane == 0) out[warp * DPAD] = t;
#pragma unroll
    for (int j = 0; j < 4; j++) {
        int c = lane + 32 * j;
        if (c < DS) out[warp * DPAD + 1 + c] = f * v[j];
    }
}

extern "C" void kernel_launch(void* const* d_in, const int* in_sizes, int n_in,
                              void* d_out, int out_size) {
    const float* x  = (const float*)d_in[0];
    const float* W1 = (const float*)d_in[1];
    const float* b1 = (const float*)d_in[2];
    const float* W2 = (const float*)d_in[3];
    const float* b2 = (const float*)d_in[4];
    const int*   es = (const int*)d_in[5];
    const int*   ed = (const int*)d_in[6];
    const float* ew = (const float*)d_in[7];
    float* out = (float*)d_out;

    const int smem_bytes = (DS * DPAD + GEMM_ROWS * DPAD + DPAD) * (int)sizeof(float);
    cudaFuncSetAttribute(k_gemm, cudaFuncAttributeMaxDynamicSharedMemorySize, smem_bytes);

    int row_blocks  = (N_NODES * 32 + 255) / 256;   // warp per row
    int gemm_blocks = (N_NODES + GEMM_ROWS - 1) / GEMM_ROWS;
    int edge_blocks = (NE * 32 + 255) / 256;        // warp per edge

    k_init<<<row_blocks, 256>>>(x);

    k_gemm<<<gemm_blocks, 256, smem_bytes>>>(W1, b1);
    k_edge<<<edge_blocks, 256>>>(es, ed, ew);
    k_post<<<row_blocks, 256>>>();

    k_gemm<<<gemm_blocks, 256, smem_bytes>>>(W2, b2);
    k_edge<<<edge_blocks, 256>>>(es, ed, ew);
    k_post<<<row_blocks, 256>>>();

    k_final<<<row_blocks, 256>>>(out);
}